// round 12
// baseline (speedup 1.0000x reference)
#include <cuda_runtime.h>

#define NCAM 6
#define C    64
#define HF   64
#define WF   176
#define NY   4
#define ZD   129
#define XD   129
#define NH   3
#define DD   128
#define WDIM 128
#define NVOX (NH * DD * WDIM)   // 49152

// Scratch (static device globals: allocation-free per harness rules)
__device__ float  g_tmpi[NCAM * C * HF * WF];    // [n][c][h][w]
__device__ float  g_integ[NCAM * HF * WF * C];   // [n][h][w][c]
__device__ float2 g_nc[NCAM * NY * ZD * XD];     // projected corners

// ---------------------------------------------------------------------------
// Kernel 1a: row-wise inclusive scan. Warp per row, no smem.
// rows = NCAM*C*HF = 24576; block = 8 warps -> 3072 blocks.
// ---------------------------------------------------------------------------
__global__ void __launch_bounds__(256) rowscan_kernel(const float* __restrict__ feat) {
    const int lane = threadIdx.x & 31;
    const int wp   = threadIdx.x >> 5;
    const int row  = blockIdx.x * 8 + wp;        // < 24576 always (exact)

    const float* src = feat  + (size_t)row * WF;
    float*       dst = g_tmpi + (size_t)row * WF;

    float carry = 0.f;
    #pragma unroll
    for (int seg = 0; seg < 6; seg++) {
        const int w = seg * 32 + lane;
        float v = (w < WF) ? __ldg(src + w) : 0.f;
        #pragma unroll
        for (int off = 1; off < 32; off <<= 1) {
            float u = __shfl_up_sync(0xffffffffu, v, off);
            if (lane >= off) v += u;
        }
        v += carry;
        if (w < WF) dst[w] = v;
        carry = __shfl_sync(0xffffffffu, v, 31);
    }
}

// ---------------------------------------------------------------------------
// Kernel 1b: column-wise inclusive scan, in place on g_tmpi.
// Thread per (n,c,w) column; serial over h, x4 unrolled (independent LDGs).
// Coalesced 128B per warp per step. 67584 threads.
// ---------------------------------------------------------------------------
__global__ void __launch_bounds__(256) colscan_kernel() {
    const int idx = blockIdx.x * 256 + threadIdx.x;
    if (idx >= NCAM * C * WF) return;
    const int nc = idx / WF;
    const int w  = idx - nc * WF;

    float* p = g_tmpi + (size_t)nc * HF * WF + w;
    float acc = 0.f;
    #pragma unroll 1
    for (int h = 0; h < HF; h += 4) {
        float v0 = p[0];
        float v1 = p[WF];
        float v2 = p[2 * WF];
        float v3 = p[3 * WF];
        acc += v0; p[0]      = acc;
        acc += v1; p[WF]     = acc;
        acc += v2; p[2 * WF] = acc;
        acc += v3; p[3 * WF] = acc;
        p += 4 * WF;
    }
}

// ---------------------------------------------------------------------------
// Kernel 2 (fused): blocks [0, 2304) transpose [n][c][h][w] -> [n][h][w][c];
// blocks [2304, ...) project grid corners. Independent work, one launch.
// ---------------------------------------------------------------------------
#define NTRANS (6 * HF * NCAM)   // 2304 transpose blocks
__global__ void __launch_bounds__(256) transproj_kernel(
        const float* __restrict__ ks,
        const float* __restrict__ m2c,
        const float* __restrict__ prot,
        const float* __restrict__ ptran,
        const float* __restrict__ und,
        const float* __restrict__ grid) {
    __shared__ float tile[C * 33];
    const int bid = blockIdx.x;

    if (bid < NTRANS) {
        // ---- transpose ----
        const int wt = bid % 6;
        const int h  = (bid / 6) % HF;
        const int n  = bid / (6 * HF);
        const int w0 = wt * 32;

        const float* src = g_tmpi + ((size_t)n * C * HF + h) * WF;
        for (int idx = threadIdx.x; idx < C * 32; idx += 256) {
            int c = idx >> 5, w = idx & 31;
            int gw = w0 + w;
            tile[c * 33 + w] = (gw < WF) ? src[(size_t)c * HF * WF + gw] : 0.f;
        }
        __syncthreads();

        float* dst = g_integ + (((size_t)n * HF + h) * WF) * C;
        for (int idx = threadIdx.x; idx < C * 32; idx += 256) {
            int w = idx >> 6, c = idx & 63;
            int gw = w0 + w;
            if (gw < WF) dst[(size_t)gw * C + c] = tile[c * 33 + w];
        }
        return;
    }

    // ---- projection ----
    const int id = (bid - NTRANS) * 256 + threadIdx.x;
    const int total = NCAM * NY * ZD * XD;
    if (id >= total) return;
    const int xi = id % XD;
    const int zi = (id / XD) % ZD;
    const int ny = (id / (XD * ZD)) % NY;
    const int n  = id / (XD * ZD * NY);

    const float* K  = ks    + n * 9;
    const float* M  = m2c   + n * 12;
    const float* PR = prot  + n * 9;
    const float* PT = ptran + n * 3;
    const float* Dd = und   + n * 7;

    float cal[3][4];
    #pragma unroll
    for (int i = 0; i < 3; i++)
        #pragma unroll
        for (int j = 0; j < 4; j++)
            cal[i][j] = K[i*3+0]*M[0*4+j] + K[i*3+1]*M[1*4+j] + K[i*3+2]*M[2*4+j];

    const float* g = grid + ((size_t)zi * XD + xi) * 3;
    const float vx = g[0];
    const float vy = g[1] + (2.0f - (float)ny);
    const float vz = g[2];

    float hx = cal[0][0]*vx + cal[0][1]*vy + cal[0][2]*vz + cal[0][3];
    float hy = cal[1][0]*vx + cal[1][1]*vy + cal[1][2]*vz + cal[1][3];
    float hz = cal[2][0]*vx + cal[2][1]*vy + cal[2][2]*vz + cal[2][3];

    const float posf = (hz > 0.f) ? 1.f : 0.f;
    hx *= posf; hy *= posf;
    const float px = hx / hz, py = hy / hz;

    const float cx = K[2], cy = K[5], fx = K[0], fy = K[4];
    const float x = (px - cx) / fx, y = (py - cy) / fy;

    float xd, yd;
    if (Dd[6] == 1.0f) {
        float r  = sqrtf(x*x + y*y);
        float th = atanf(r);
        float t2 = th * th;
        float t4 = t2 * t2;
        float rad = th * (1.f + Dd[0]*t2 + Dd[1]*t4 + Dd[2]*t4*t2 + Dd[5]*t4*t4) / r;
        xd = x * rad * fx + cx;
        yd = y * rad * fy + cy;
    } else {
        float r2 = x*x + y*y;
        float r4 = r2 * r2;
        float poly = 1.f + Dd[0]*r2 + Dd[1]*r4 + Dd[2]*r4*r2;
        float p1 = Dd[3], p2 = Dd[4];
        float xdd = x*poly + (2.f*p1*x*y + p2*(r2 + 2.f*x*x));
        float ydd = y*poly + (p1*(r2 + 2.f*y*y) + 2.f*p2*x*y);
        xd = xdd * fx + cx;
        yd = ydd * fy + cy;
    }
    xd *= posf; yd *= posf;

    const float qx = PR[0]*xd + PR[1]*yd + PT[0];
    const float qy = PR[3]*xd + PR[4]*yd + PT[1];

    float2 o;
    o.x = fminf(fmaxf(2.f*qx - 1.f, -1.f), 1.f);
    o.y = fminf(fmaxf(2.f*qy - 1.f, -1.f), 1.f);
    g_nc[id] = o;
}

// ---------------------------------------------------------------------------
// Kernel 3 (R6 proven form): fused geometry (smem descriptors, 48 tasks per
// block) + gather. 16 independent unrolled loads per cam, coefficients
// pre-combined with 1/area; max over cameras.
// ---------------------------------------------------------------------------
__global__ void __launch_bounds__(256) vox_kernel(float* __restrict__ out) {
    const int nhd = blockIdx.x >> 4;
    const int d   = nhd & 127;
    const int nh  = nhd >> 7;
    const int wd0 = (blockIdx.x & 15) << 3;
    const int tid = threadIdx.y * 32 + threadIdx.x;

    __shared__ int   s_off[48 * 16];    // texel offsets (float2 units)
    __shared__ float s_c[48 * 16];      // combined coefficients
    __shared__ int   s_act[48];         // active flag per (cam,voxel)
    __shared__ float res[C * 9];        // output staging

    // ---- Geometry phase: one task per thread, task = cam*8 + vy ----
    if (tid < 48) {
        const int cam = tid >> 3, vy = tid & 7;
        const int wd = wd0 + vy;
        const float2* ncp = g_nc + cam * (NY * ZD * XD) + ((size_t)nh * ZD + d) * XD + wd;

        float l = 1e30f, r = -1e30f, tp = 1e30f, bt = -1e30f;
        #pragma unroll
        for (int a = 0; a < 2; a++)
            #pragma unroll
            for (int b = 0; b < 2; b++)
                #pragma unroll
                for (int cc2 = 0; cc2 < 2; cc2++) {
                    float2 p = __ldg(ncp + (a * ZD + b) * XD + cc2);
                    l  = fminf(l,  p.x); r  = fmaxf(r,  p.x);
                    tp = fminf(tp, p.y); bt = fmaxf(bt, p.y);
                }

        const float area = (r - l) * (bt - tp) * (HF * WF * 0.25f) + 1e-6f;
        const int ok = (area > 1e-6f) ? 1 : 0;
        s_act[tid] = ok;
        if (ok) {
            float pxl = fminf(fmaxf((l  + 1.f) * 87.5f, 0.f), 175.f);
            float pxr = fminf(fmaxf((r  + 1.f) * 87.5f, 0.f), 175.f);
            float pyt = fminf(fmaxf((tp + 1.f) * 31.5f, 0.f), 63.f);
            float pyb = fminf(fmaxf((bt + 1.f) * 31.5f, 0.f), 63.f);

            float fxl = floorf(pxl), fxr = floorf(pxr);
            float fyt = floorf(pyt), fyb = floorf(pyb);
            float wxl = pxl - fxl, wxr = pxr - fxr;
            float wyt = pyt - fyt, wyb = pyb - fyb;

            int xs[4], ys[4];
            xs[0] = (int)fxl; xs[1] = min(xs[0] + 1, WF - 1);
            xs[2] = (int)fxr; xs[3] = min(xs[2] + 1, WF - 1);
            ys[0] = (int)fyt; ys[1] = min(ys[0] + 1, HF - 1);
            ys[2] = (int)fyb; ys[3] = min(ys[2] + 1, HF - 1);

            const float inv = 1.0f / area;
            float cxv[4] = {1.f - wxl, wxl, -(1.f - wxr), -wxr};
            float cyv[4] = {(1.f - wyt) * inv, wyt * inv,
                            -(1.f - wyb) * inv, -wyb * inv};

            #pragma unroll
            for (int i = 0; i < 4; i++) {
                const int yb = ys[i] * WF;
                #pragma unroll
                for (int j = 0; j < 4; j++) {
                    s_off[tid * 16 + i * 4 + j] = (yb + xs[j]) * (C / 2);
                    s_c[tid * 16 + i * 4 + j]   = cyv[i] * cxv[j];
                }
            }
        }
    }
    __syncthreads();

    // ---- Gather phase ----
    const int t = threadIdx.x;                   // channel pair
    float m0 = -3.402823466e38f, m1 = -3.402823466e38f;

    #pragma unroll 1
    for (int n = 0; n < NCAM; n++) {
        const int task = n * 8 + threadIdx.y;
        if (!s_act[task]) {
            m0 = fmaxf(m0, 0.f);
            m1 = fmaxf(m1, 0.f);
            continue;
        }
        const int4*   so = (const int4*)  (s_off + task * 16);
        const float4* sc = (const float4*)(s_c   + task * 16);
        const float2* base = (const float2*)(g_integ + (size_t)n * HF * WF * C) + t;

        float nx = 0.f, nyv = 0.f;
        #pragma unroll
        for (int g = 0; g < 4; g++) {
            const int4   o  = so[g];
            const float4 cc = sc[g];
            float2 a = __ldg(base + o.x), b = __ldg(base + o.y);
            float2 c = __ldg(base + o.z), e = __ldg(base + o.w);
            nx  = fmaf(a.x, cc.x, fmaf(b.x, cc.y, fmaf(c.x, cc.z, fmaf(e.x, cc.w, nx))));
            nyv = fmaf(a.y, cc.x, fmaf(b.y, cc.y, fmaf(c.y, cc.z, fmaf(e.y, cc.w, nyv))));
        }
        m0 = fmaxf(m0, nx);
        m1 = fmaxf(m1, nyv);
    }

    // ---- Output staging: coalesced 32B segments ----
    res[(2 * t    ) * 9 + threadIdx.y] = m0;
    res[(2 * t + 1) * 9 + threadIdx.y] = m1;
    __syncthreads();

    #pragma unroll
    for (int rep = 0; rep < 2; rep++) {
        int idx = tid + rep * 256;               // 0..511 = c*8 + j
        int ch  = idx >> 3;
        int j   = idx & 7;
        out[((size_t)(ch * NH + nh) * DD + d) * WDIM + wd0 + j] = res[ch * 9 + j];
    }
}

// ---------------------------------------------------------------------------
extern "C" void kernel_launch(void* const* d_in, const int* in_sizes, int n_in,
                              void* d_out, int out_size) {
    (void)in_sizes; (void)n_in; (void)out_size;
    const float* features  = (const float*)d_in[0];
    const float* ks        = (const float*)d_in[1];
    const float* imu2cs    = (const float*)d_in[2];
    const float* post_rots = (const float*)d_in[3];
    const float* post_trans= (const float*)d_in[4];
    const float* undists   = (const float*)d_in[5];
    const float* grid      = (const float*)d_in[6];
    float* out = (float*)d_out;

    rowscan_kernel<<<NCAM * C * HF / 8, 256>>>(features);

    colscan_kernel<<<(NCAM * C * WF + 255) / 256, 256>>>();

    const int totalP = NCAM * NY * ZD * XD;
    const int projBlocks = (totalP + 255) / 256;     // 1561
    transproj_kernel<<<NTRANS + projBlocks, 256>>>(ks, imu2cs, post_rots,
                                                   post_trans, undists, grid);

    dim3 blk(32, 8);
    vox_kernel<<<(NH * DD * WDIM) / 8, blk>>>(out);
}

// round 13
// speedup vs baseline: 1.1449x; 1.1449x over previous
#include <cuda_runtime.h>

#define NCAM 6
#define C    64
#define HF   64
#define WF   176
#define NY   4
#define ZD   129
#define XD   129
#define NH   3
#define DD   128
#define WDIM 128
#define NVOX (NH * DD * WDIM)   // 49152
#define SPITCH 180              // smem pitch: 20*dcl mod 32 conflict-free

// Scratch (static device globals: allocation-free per harness rules)
__device__ float  g_integ[NCAM * HF * WF * C];   // [n][h][w][c]
__device__ float2 g_nc[NCAM * NY * ZD * XD];     // projected corners

// ---------------------------------------------------------------------------
// Kernel 1: row-wise inclusive scan, written DIRECTLY channels-last.
// Block = (n, h, channel-block of 8). 8 warps scan 8 rows -> smem tile ->
// transposed write in 32B-contiguous 8-channel groups.
// Grid = NCAM * HF * (C/8) = 3072 blocks.
// ---------------------------------------------------------------------------
__global__ void __launch_bounds__(256) rowscan_t_kernel(const float* __restrict__ feat) {
    __shared__ float tile[8 * SPITCH];
    const int bid = blockIdx.x;
    const int cb  = bid & 7;                 // channel block (8 channels)
    const int h   = (bid >> 3) & (HF - 1);
    const int n   = bid >> 9;                // bid / (HF*8)
    const int lane = threadIdx.x & 31;
    const int wp   = threadIdx.x >> 5;       // warp -> local channel
    const int c    = cb * 8 + wp;

    const float* src = feat + (((size_t)(n * C + c) * HF) + h) * WF;

    float carry = 0.f;
    #pragma unroll
    for (int seg = 0; seg < 6; seg++) {
        const int w = seg * 32 + lane;
        float v = (w < WF) ? __ldg(src + w) : 0.f;
        #pragma unroll
        for (int off = 1; off < 32; off <<= 1) {
            float u = __shfl_up_sync(0xffffffffu, v, off);
            if (lane >= off) v += u;
        }
        v += carry;
        if (w < WF) tile[wp * SPITCH + w] = v;
        carry = __shfl_sync(0xffffffffu, v, 31);
    }
    __syncthreads();

    // Transposed write: idx -> (w, cl); 8 consecutive threads write 32B run.
    float* dst = g_integ + (((size_t)n * HF + h) * WF) * C + cb * 8;
    for (int i = threadIdx.x; i < 8 * WF; i += 256) {
        const int cl = i & 7;
        const int w  = i >> 3;
        dst[(size_t)w * C + cl] = tile[cl * SPITCH + w];
    }
}

// ---------------------------------------------------------------------------
// Kernel 2 (fused): blocks [0, 264) column-scan g_integ in place over h
// (thread per (n,w,c), coalesced 128B steps, x4 unroll);
// blocks [264, ...) project grid corners.
// ---------------------------------------------------------------------------
#define NCOLB (NCAM * WF * C / 256)   // 264 column-scan blocks (exact)
__global__ void __launch_bounds__(256) colproj_kernel(
        const float* __restrict__ ks,
        const float* __restrict__ m2c,
        const float* __restrict__ prot,
        const float* __restrict__ ptran,
        const float* __restrict__ und,
        const float* __restrict__ grid) {
    const int bid = blockIdx.x;

    if (bid < NCOLB) {
        // ---- column scan ----
        const int idx = bid * 256 + threadIdx.x;     // = (n*WF + w)*C + c
        const int n   = idx / (WF * C);
        const int rem = idx - n * (WF * C);          // w*C + c
        float* p = g_integ + (size_t)n * HF * WF * C + rem;
        const int stride = WF * C;

        float acc = 0.f;
        #pragma unroll 1
        for (int h = 0; h < HF; h += 4) {
            float v0 = p[0];
            float v1 = p[stride];
            float v2 = p[2 * stride];
            float v3 = p[3 * stride];
            acc += v0; p[0]          = acc;
            acc += v1; p[stride]     = acc;
            acc += v2; p[2 * stride] = acc;
            acc += v3; p[3 * stride] = acc;
            p += 4 * stride;
        }
        return;
    }

    // ---- projection ----
    const int id = (bid - NCOLB) * 256 + threadIdx.x;
    const int total = NCAM * NY * ZD * XD;
    if (id >= total) return;
    const int xi = id % XD;
    const int zi = (id / XD) % ZD;
    const int ny = (id / (XD * ZD)) % NY;
    const int n  = id / (XD * ZD * NY);

    const float* K  = ks    + n * 9;
    const float* M  = m2c   + n * 12;
    const float* PR = prot  + n * 9;
    const float* PT = ptran + n * 3;
    const float* Dd = und   + n * 7;

    float cal[3][4];
    #pragma unroll
    for (int i = 0; i < 3; i++)
        #pragma unroll
        for (int j = 0; j < 4; j++)
            cal[i][j] = K[i*3+0]*M[0*4+j] + K[i*3+1]*M[1*4+j] + K[i*3+2]*M[2*4+j];

    const float* g = grid + ((size_t)zi * XD + xi) * 3;
    const float vx = g[0];
    const float vy = g[1] + (2.0f - (float)ny);
    const float vz = g[2];

    float hx = cal[0][0]*vx + cal[0][1]*vy + cal[0][2]*vz + cal[0][3];
    float hy = cal[1][0]*vx + cal[1][1]*vy + cal[1][2]*vz + cal[1][3];
    float hz = cal[2][0]*vx + cal[2][1]*vy + cal[2][2]*vz + cal[2][3];

    const float posf = (hz > 0.f) ? 1.f : 0.f;
    hx *= posf; hy *= posf;
    const float px = hx / hz, py = hy / hz;

    const float cx = K[2], cy = K[5], fx = K[0], fy = K[4];
    const float x = (px - cx) / fx, y = (py - cy) / fy;

    float xd, yd;
    if (Dd[6] == 1.0f) {
        float r  = sqrtf(x*x + y*y);
        float th = atanf(r);
        float t2 = th * th;
        float t4 = t2 * t2;
        float rad = th * (1.f + Dd[0]*t2 + Dd[1]*t4 + Dd[2]*t4*t2 + Dd[5]*t4*t4) / r;
        xd = x * rad * fx + cx;
        yd = y * rad * fy + cy;
    } else {
        float r2 = x*x + y*y;
        float r4 = r2 * r2;
        float poly = 1.f + Dd[0]*r2 + Dd[1]*r4 + Dd[2]*r4*r2;
        float p1 = Dd[3], p2 = Dd[4];
        float xdd = x*poly + (2.f*p1*x*y + p2*(r2 + 2.f*x*x));
        float ydd = y*poly + (p1*(r2 + 2.f*y*y) + 2.f*p2*x*y);
        xd = xdd * fx + cx;
        yd = ydd * fy + cy;
    }
    xd *= posf; yd *= posf;

    const float qx = PR[0]*xd + PR[1]*yd + PT[0];
    const float qy = PR[3]*xd + PR[4]*yd + PT[1];

    float2 o;
    o.x = fminf(fmaxf(2.f*qx - 1.f, -1.f), 1.f);
    o.y = fminf(fmaxf(2.f*qy - 1.f, -1.f), 1.f);
    g_nc[id] = o;
}

// ---------------------------------------------------------------------------
// Kernel 3 (proven form): fused geometry (smem descriptors, 48 tasks per
// block) + gather. 16 independent unrolled loads per cam, coefficients
// pre-combined with 1/area; max over cameras.
// ---------------------------------------------------------------------------
__global__ void __launch_bounds__(256) vox_kernel(float* __restrict__ out) {
    const int nhd = blockIdx.x >> 4;
    const int d   = nhd & 127;
    const int nh  = nhd >> 7;
    const int wd0 = (blockIdx.x & 15) << 3;
    const int tid = threadIdx.y * 32 + threadIdx.x;

    __shared__ int   s_off[48 * 16];    // texel offsets (float2 units)
    __shared__ float s_c[48 * 16];      // combined coefficients
    __shared__ int   s_act[48];         // active flag per (cam,voxel)
    __shared__ float res[C * 9];        // output staging

    // ---- Geometry phase: one task per thread, task = cam*8 + vy ----
    if (tid < 48) {
        const int cam = tid >> 3, vy = tid & 7;
        const int wd = wd0 + vy;
        const float2* ncp = g_nc + cam * (NY * ZD * XD) + ((size_t)nh * ZD + d) * XD + wd;

        float l = 1e30f, r = -1e30f, tp = 1e30f, bt = -1e30f;
        #pragma unroll
        for (int a = 0; a < 2; a++)
            #pragma unroll
            for (int b = 0; b < 2; b++)
                #pragma unroll
                for (int cc2 = 0; cc2 < 2; cc2++) {
                    float2 p = __ldg(ncp + (a * ZD + b) * XD + cc2);
                    l  = fminf(l,  p.x); r  = fmaxf(r,  p.x);
                    tp = fminf(tp, p.y); bt = fmaxf(bt, p.y);
                }

        const float area = (r - l) * (bt - tp) * (HF * WF * 0.25f) + 1e-6f;
        const int ok = (area > 1e-6f) ? 1 : 0;
        s_act[tid] = ok;
        if (ok) {
            float pxl = fminf(fmaxf((l  + 1.f) * 87.5f, 0.f), 175.f);
            float pxr = fminf(fmaxf((r  + 1.f) * 87.5f, 0.f), 175.f);
            float pyt = fminf(fmaxf((tp + 1.f) * 31.5f, 0.f), 63.f);
            float pyb = fminf(fmaxf((bt + 1.f) * 31.5f, 0.f), 63.f);

            float fxl = floorf(pxl), fxr = floorf(pxr);
            float fyt = floorf(pyt), fyb = floorf(pyb);
            float wxl = pxl - fxl, wxr = pxr - fxr;
            float wyt = pyt - fyt, wyb = pyb - fyb;

            int xs[4], ys[4];
            xs[0] = (int)fxl; xs[1] = min(xs[0] + 1, WF - 1);
            xs[2] = (int)fxr; xs[3] = min(xs[2] + 1, WF - 1);
            ys[0] = (int)fyt; ys[1] = min(ys[0] + 1, HF - 1);
            ys[2] = (int)fyb; ys[3] = min(ys[2] + 1, HF - 1);

            const float inv = 1.0f / area;
            float cxv[4] = {1.f - wxl, wxl, -(1.f - wxr), -wxr};
            float cyv[4] = {(1.f - wyt) * inv, wyt * inv,
                            -(1.f - wyb) * inv, -wyb * inv};

            #pragma unroll
            for (int i = 0; i < 4; i++) {
                const int yb = ys[i] * WF;
                #pragma unroll
                for (int j = 0; j < 4; j++) {
                    s_off[tid * 16 + i * 4 + j] = (yb + xs[j]) * (C / 2);
                    s_c[tid * 16 + i * 4 + j]   = cyv[i] * cxv[j];
                }
            }
        }
    }
    __syncthreads();

    // ---- Gather phase ----
    const int t = threadIdx.x;                   // channel pair
    float m0 = -3.402823466e38f, m1 = -3.402823466e38f;

    #pragma unroll 1
    for (int n = 0; n < NCAM; n++) {
        const int task = n * 8 + threadIdx.y;
        if (!s_act[task]) {
            m0 = fmaxf(m0, 0.f);
            m1 = fmaxf(m1, 0.f);
            continue;
        }
        const int4*   so = (const int4*)  (s_off + task * 16);
        const float4* sc = (const float4*)(s_c   + task * 16);
        const float2* base = (const float2*)(g_integ + (size_t)n * HF * WF * C) + t;

        float nx = 0.f, nyv = 0.f;
        #pragma unroll
        for (int g = 0; g < 4; g++) {
            const int4   o  = so[g];
            const float4 cc = sc[g];
            float2 a = __ldg(base + o.x), b = __ldg(base + o.y);
            float2 c = __ldg(base + o.z), e = __ldg(base + o.w);
            nx  = fmaf(a.x, cc.x, fmaf(b.x, cc.y, fmaf(c.x, cc.z, fmaf(e.x, cc.w, nx))));
            nyv = fmaf(a.y, cc.x, fmaf(b.y, cc.y, fmaf(c.y, cc.z, fmaf(e.y, cc.w, nyv))));
        }
        m0 = fmaxf(m0, nx);
        m1 = fmaxf(m1, nyv);
    }

    // ---- Output staging: coalesced 32B segments ----
    res[(2 * t    ) * 9 + threadIdx.y] = m0;
    res[(2 * t + 1) * 9 + threadIdx.y] = m1;
    __syncthreads();

    #pragma unroll
    for (int rep = 0; rep < 2; rep++) {
        int idx = tid + rep * 256;               // 0..511 = c*8 + j
        int ch  = idx >> 3;
        int j   = idx & 7;
        out[((size_t)(ch * NH + nh) * DD + d) * WDIM + wd0 + j] = res[ch * 9 + j];
    }
}

// ---------------------------------------------------------------------------
extern "C" void kernel_launch(void* const* d_in, const int* in_sizes, int n_in,
                              void* d_out, int out_size) {
    (void)in_sizes; (void)n_in; (void)out_size;
    const float* features  = (const float*)d_in[0];
    const float* ks        = (const float*)d_in[1];
    const float* imu2cs    = (const float*)d_in[2];
    const float* post_rots = (const float*)d_in[3];
    const float* post_trans= (const float*)d_in[4];
    const float* undists   = (const float*)d_in[5];
    const float* grid      = (const float*)d_in[6];
    float* out = (float*)d_out;

    rowscan_t_kernel<<<NCAM * HF * (C / 8), 256>>>(features);

    const int totalP = NCAM * NY * ZD * XD;
    const int projBlocks = (totalP + 255) / 256;     // 1561
    colproj_kernel<<<NCOLB + projBlocks, 256>>>(ks, imu2cs, post_rots,
                                                post_trans, undists, grid);

    dim3 blk(32, 8);
    vox_kernel<<<(NH * DD * WDIM) / 8, blk>>>(out);
}

// round 14
// speedup vs baseline: 1.1466x; 1.0015x over previous
#include <cuda_runtime.h>

#define NCAM 6
#define C    64
#define HF   64
#define WF   176
#define NY   4
#define ZD   129
#define XD   129
#define NH   3
#define DD   128
#define WDIM 128
#define NVOX (NH * DD * WDIM)   // 49152
#define SPITCH 180              // smem pitch: 20*dcl mod 32 conflict-free

// Scratch (static device globals: allocation-free per harness rules)
__device__ float  g_integ[NCAM * HF * WF * C];   // [n][h][w][c]
__device__ float2 g_nc[NCAM * NY * ZD * XD];     // projected corners

// ---------------------------------------------------------------------------
// Kernel 1: row-wise inclusive scan, written DIRECTLY channels-last.
// Block = (n, h, channel-block of 8). 8 warps scan 8 rows -> smem tile ->
// transposed write via float4 (STG.128, 4x fewer store instructions).
// Grid = NCAM * HF * (C/8) = 3072 blocks.
// ---------------------------------------------------------------------------
__global__ void __launch_bounds__(256) rowscan_t_kernel(const float* __restrict__ feat) {
    __shared__ float tile[8 * SPITCH];
    const int bid = blockIdx.x;
    const int cb  = bid & 7;                 // channel block (8 channels)
    const int h   = (bid >> 3) & (HF - 1);
    const int n   = bid >> 9;                // bid / (HF*8)
    const int lane = threadIdx.x & 31;
    const int wp   = threadIdx.x >> 5;       // warp -> local channel
    const int c    = cb * 8 + wp;

    const float* src = feat + (((size_t)(n * C + c) * HF) + h) * WF;

    float carry = 0.f;
    #pragma unroll
    for (int seg = 0; seg < 6; seg++) {
        const int w = seg * 32 + lane;
        float v = (w < WF) ? __ldg(src + w) : 0.f;
        #pragma unroll
        for (int off = 1; off < 32; off <<= 1) {
            float u = __shfl_up_sync(0xffffffffu, v, off);
            if (lane >= off) v += u;
        }
        v += carry;
        if (w < WF) tile[wp * SPITCH + w] = v;
        carry = __shfl_sync(0xffffffffu, v, 31);
    }
    __syncthreads();

    // Transposed write: task = (w, channel-group of 4). 2*WF = 352 tasks.
    // LDS banks conflict-free (see analysis); STG.128 -> 16x32B sectors/warp.
    float4* dst4 = (float4*)(g_integ + (((size_t)n * HF + h) * WF) * C + cb * 8);
    #pragma unroll
    for (int iter = 0; iter < 2; iter++) {
        const int idx = threadIdx.x + iter * 256;
        if (idx < 2 * WF) {
            const int grp = idx & 1;
            const int w   = idx >> 1;
            const float* trow = tile + (grp * 4) * SPITCH + w;
            float4 v;
            v.x = trow[0];
            v.y = trow[SPITCH];
            v.z = trow[2 * SPITCH];
            v.w = trow[3 * SPITCH];
            dst4[(size_t)w * (C / 4) + grp] = v;
        }
    }
}

// ---------------------------------------------------------------------------
// Kernel 2 (fused): blocks [0, 264) column-scan g_integ in place over h
// (thread per (n,w,c), coalesced 128B steps, x8 unroll for MLP);
// blocks [264, ...) project grid corners.
// ---------------------------------------------------------------------------
#define NCOLB (NCAM * WF * C / 256)   // 264 column-scan blocks (exact)
__global__ void __launch_bounds__(256) colproj_kernel(
        const float* __restrict__ ks,
        const float* __restrict__ m2c,
        const float* __restrict__ prot,
        const float* __restrict__ ptran,
        const float* __restrict__ und,
        const float* __restrict__ grid) {
    const int bid = blockIdx.x;

    if (bid < NCOLB) {
        // ---- column scan ----
        const int idx = bid * 256 + threadIdx.x;     // = (n*WF + w)*C + c
        const int n   = idx / (WF * C);
        const int rem = idx - n * (WF * C);          // w*C + c
        float* p = g_integ + (size_t)n * HF * WF * C + rem;
        const int stride = WF * C;

        float acc = 0.f;
        #pragma unroll 1
        for (int h = 0; h < HF; h += 8) {
            float v0 = p[0];
            float v1 = p[stride];
            float v2 = p[2 * stride];
            float v3 = p[3 * stride];
            float v4 = p[4 * stride];
            float v5 = p[5 * stride];
            float v6 = p[6 * stride];
            float v7 = p[7 * stride];
            acc += v0; p[0]          = acc;
            acc += v1; p[stride]     = acc;
            acc += v2; p[2 * stride] = acc;
            acc += v3; p[3 * stride] = acc;
            acc += v4; p[4 * stride] = acc;
            acc += v5; p[5 * stride] = acc;
            acc += v6; p[6 * stride] = acc;
            acc += v7; p[7 * stride] = acc;
            p += 8 * stride;
        }
        return;
    }

    // ---- projection ----
    const int id = (bid - NCOLB) * 256 + threadIdx.x;
    const int total = NCAM * NY * ZD * XD;
    if (id >= total) return;
    const int xi = id % XD;
    const int zi = (id / XD) % ZD;
    const int ny = (id / (XD * ZD)) % NY;
    const int n  = id / (XD * ZD * NY);

    const float* K  = ks    + n * 9;
    const float* M  = m2c   + n * 12;
    const float* PR = prot  + n * 9;
    const float* PT = ptran + n * 3;
    const float* Dd = und   + n * 7;

    float cal[3][4];
    #pragma unroll
    for (int i = 0; i < 3; i++)
        #pragma unroll
        for (int j = 0; j < 4; j++)
            cal[i][j] = K[i*3+0]*M[0*4+j] + K[i*3+1]*M[1*4+j] + K[i*3+2]*M[2*4+j];

    const float* g = grid + ((size_t)zi * XD + xi) * 3;
    const float vx = g[0];
    const float vy = g[1] + (2.0f - (float)ny);
    const float vz = g[2];

    float hx = cal[0][0]*vx + cal[0][1]*vy + cal[0][2]*vz + cal[0][3];
    float hy = cal[1][0]*vx + cal[1][1]*vy + cal[1][2]*vz + cal[1][3];
    float hz = cal[2][0]*vx + cal[2][1]*vy + cal[2][2]*vz + cal[2][3];

    const float posf = (hz > 0.f) ? 1.f : 0.f;
    hx *= posf; hy *= posf;
    const float px = hx / hz, py = hy / hz;

    const float cx = K[2], cy = K[5], fx = K[0], fy = K[4];
    const float x = (px - cx) / fx, y = (py - cy) / fy;

    float xd, yd;
    if (Dd[6] == 1.0f) {
        float r  = sqrtf(x*x + y*y);
        float th = atanf(r);
        float t2 = th * th;
        float t4 = t2 * t2;
        float rad = th * (1.f + Dd[0]*t2 + Dd[1]*t4 + Dd[2]*t4*t2 + Dd[5]*t4*t4) / r;
        xd = x * rad * fx + cx;
        yd = y * rad * fy + cy;
    } else {
        float r2 = x*x + y*y;
        float r4 = r2 * r2;
        float poly = 1.f + Dd[0]*r2 + Dd[1]*r4 + Dd[2]*r4*r2;
        float p1 = Dd[3], p2 = Dd[4];
        float xdd = x*poly + (2.f*p1*x*y + p2*(r2 + 2.f*x*x));
        float ydd = y*poly + (p1*(r2 + 2.f*y*y) + 2.f*p2*x*y);
        xd = xdd * fx + cx;
        yd = ydd * fy + cy;
    }
    xd *= posf; yd *= posf;

    const float qx = PR[0]*xd + PR[1]*yd + PT[0];
    const float qy = PR[3]*xd + PR[4]*yd + PT[1];

    float2 o;
    o.x = fminf(fmaxf(2.f*qx - 1.f, -1.f), 1.f);
    o.y = fminf(fmaxf(2.f*qy - 1.f, -1.f), 1.f);
    g_nc[id] = o;
}

// ---------------------------------------------------------------------------
// Kernel 3 (proven form): fused geometry (smem descriptors, 48 tasks per
// block) + gather. 16 independent unrolled loads per cam, coefficients
// pre-combined with 1/area; max over cameras.
// ---------------------------------------------------------------------------
__global__ void __launch_bounds__(256) vox_kernel(float* __restrict__ out) {
    const int nhd = blockIdx.x >> 4;
    const int d   = nhd & 127;
    const int nh  = nhd >> 7;
    const int wd0 = (blockIdx.x & 15) << 3;
    const int tid = threadIdx.y * 32 + threadIdx.x;

    __shared__ int   s_off[48 * 16];    // texel offsets (float2 units)
    __shared__ float s_c[48 * 16];      // combined coefficients
    __shared__ int   s_act[48];         // active flag per (cam,voxel)
    __shared__ float res[C * 9];        // output staging

    // ---- Geometry phase: one task per thread, task = cam*8 + vy ----
    if (tid < 48) {
        const int cam = tid >> 3, vy = tid & 7;
        const int wd = wd0 + vy;
        const float2* ncp = g_nc + cam * (NY * ZD * XD) + ((size_t)nh * ZD + d) * XD + wd;

        float l = 1e30f, r = -1e30f, tp = 1e30f, bt = -1e30f;
        #pragma unroll
        for (int a = 0; a < 2; a++)
            #pragma unroll
            for (int b = 0; b < 2; b++)
                #pragma unroll
                for (int cc2 = 0; cc2 < 2; cc2++) {
                    float2 p = __ldg(ncp + (a * ZD + b) * XD + cc2);
                    l  = fminf(l,  p.x); r  = fmaxf(r,  p.x);
                    tp = fminf(tp, p.y); bt = fmaxf(bt, p.y);
                }

        const float area = (r - l) * (bt - tp) * (HF * WF * 0.25f) + 1e-6f;
        const int ok = (area > 1e-6f) ? 1 : 0;
        s_act[tid] = ok;
        if (ok) {
            float pxl = fminf(fmaxf((l  + 1.f) * 87.5f, 0.f), 175.f);
            float pxr = fminf(fmaxf((r  + 1.f) * 87.5f, 0.f), 175.f);
            float pyt = fminf(fmaxf((tp + 1.f) * 31.5f, 0.f), 63.f);
            float pyb = fminf(fmaxf((bt + 1.f) * 31.5f, 0.f), 63.f);

            float fxl = floorf(pxl), fxr = floorf(pxr);
            float fyt = floorf(pyt), fyb = floorf(pyb);
            float wxl = pxl - fxl, wxr = pxr - fxr;
            float wyt = pyt - fyt, wyb = pyb - fyb;

            int xs[4], ys[4];
            xs[0] = (int)fxl; xs[1] = min(xs[0] + 1, WF - 1);
            xs[2] = (int)fxr; xs[3] = min(xs[2] + 1, WF - 1);
            ys[0] = (int)fyt; ys[1] = min(ys[0] + 1, HF - 1);
            ys[2] = (int)fyb; ys[3] = min(ys[2] + 1, HF - 1);

            const float inv = 1.0f / area;
            float cxv[4] = {1.f - wxl, wxl, -(1.f - wxr), -wxr};
            float cyv[4] = {(1.f - wyt) * inv, wyt * inv,
                            -(1.f - wyb) * inv, -wyb * inv};

            #pragma unroll
            for (int i = 0; i < 4; i++) {
                const int yb = ys[i] * WF;
                #pragma unroll
                for (int j = 0; j < 4; j++) {
                    s_off[tid * 16 + i * 4 + j] = (yb + xs[j]) * (C / 2);
                    s_c[tid * 16 + i * 4 + j]   = cyv[i] * cxv[j];
                }
            }
        }
    }
    __syncthreads();

    // ---- Gather phase ----
    const int t = threadIdx.x;                   // channel pair
    float m0 = -3.402823466e38f, m1 = -3.402823466e38f;

    #pragma unroll 1
    for (int n = 0; n < NCAM; n++) {
        const int task = n * 8 + threadIdx.y;
        if (!s_act[task]) {
            m0 = fmaxf(m0, 0.f);
            m1 = fmaxf(m1, 0.f);
            continue;
        }
        const int4*   so = (const int4*)  (s_off + task * 16);
        const float4* sc = (const float4*)(s_c   + task * 16);
        const float2* base = (const float2*)(g_integ + (size_t)n * HF * WF * C) + t;

        float nx = 0.f, nyv = 0.f;
        #pragma unroll
        for (int g = 0; g < 4; g++) {
            const int4   o  = so[g];
            const float4 cc = sc[g];
            float2 a = __ldg(base + o.x), b = __ldg(base + o.y);
            float2 c = __ldg(base + o.z), e = __ldg(base + o.w);
            nx  = fmaf(a.x, cc.x, fmaf(b.x, cc.y, fmaf(c.x, cc.z, fmaf(e.x, cc.w, nx))));
            nyv = fmaf(a.y, cc.x, fmaf(b.y, cc.y, fmaf(c.y, cc.z, fmaf(e.y, cc.w, nyv))));
        }
        m0 = fmaxf(m0, nx);
        m1 = fmaxf(m1, nyv);
    }

    // ---- Output staging: coalesced 32B segments ----
    res[(2 * t    ) * 9 + threadIdx.y] = m0;
    res[(2 * t + 1) * 9 + threadIdx.y] = m1;
    __syncthreads();

    #pragma unroll
    for (int rep = 0; rep < 2; rep++) {
        int idx = tid + rep * 256;               // 0..511 = c*8 + j
        int ch  = idx >> 3;
        int j   = idx & 7;
        out[((size_t)(ch * NH + nh) * DD + d) * WDIM + wd0 + j] = res[ch * 9 + j];
    }
}

// ---------------------------------------------------------------------------
extern "C" void kernel_launch(void* const* d_in, const int* in_sizes, int n_in,
                              void* d_out, int out_size) {
    (void)in_sizes; (void)n_in; (void)out_size;
    const float* features  = (const float*)d_in[0];
    const float* ks        = (const float*)d_in[1];
    const float* imu2cs    = (const float*)d_in[2];
    const float* post_rots = (const float*)d_in[3];
    const float* post_trans= (const float*)d_in[4];
    const float* undists   = (const float*)d_in[5];
    const float* grid      = (const float*)d_in[6];
    float* out = (float*)d_out;

    rowscan_t_kernel<<<NCAM * HF * (C / 8), 256>>>(features);

    const int totalP = NCAM * NY * ZD * XD;
    const int projBlocks = (totalP + 255) / 256;     // 1561
    colproj_kernel<<<NCOLB + projBlocks, 256>>>(ks, imu2cs, post_rots,
                                                post_trans, undists, grid);

    dim3 blk(32, 8);
    vox_kernel<<<(NH * DD * WDIM) / 8, blk>>>(out);
}

// round 15
// speedup vs baseline: 1.1711x; 1.0213x over previous
#include <cuda_runtime.h>

#define NCAM 6
#define C    64
#define HF   64
#define WF   176
#define NY   4
#define ZD   129
#define XD   129
#define NH   3
#define DD   128
#define WDIM 128
#define NVOX (NH * DD * WDIM)   // 49152
#define SPITCH 180              // smem pitch: 20*dcl mod 32 conflict-free

// Scratch (static device globals: allocation-free per harness rules)
__device__ float  g_integ[NCAM * HF * WF * C];   // [n][h][w][c]
__device__ float2 g_nc[NCAM * NY * ZD * XD];     // projected corners

// ---------------------------------------------------------------------------
// Kernel 1: row-wise inclusive scan, written DIRECTLY channels-last.
// Block = (n, h, channel-block of 8). 8 warps scan 8 rows -> smem tile ->
// transposed write via float4 (STG.128).
// ---------------------------------------------------------------------------
__global__ void __launch_bounds__(256) rowscan_t_kernel(const float* __restrict__ feat) {
    __shared__ float tile[8 * SPITCH];
    const int bid = blockIdx.x;
    const int cb  = bid & 7;                 // channel block (8 channels)
    const int h   = (bid >> 3) & (HF - 1);
    const int n   = bid >> 9;                // bid / (HF*8)
    const int lane = threadIdx.x & 31;
    const int wp   = threadIdx.x >> 5;       // warp -> local channel
    const int c    = cb * 8 + wp;

    const float* src = feat + (((size_t)(n * C + c) * HF) + h) * WF;

    float carry = 0.f;
    #pragma unroll
    for (int seg = 0; seg < 6; seg++) {
        const int w = seg * 32 + lane;
        float v = (w < WF) ? __ldg(src + w) : 0.f;
        #pragma unroll
        for (int off = 1; off < 32; off <<= 1) {
            float u = __shfl_up_sync(0xffffffffu, v, off);
            if (lane >= off) v += u;
        }
        v += carry;
        if (w < WF) tile[wp * SPITCH + w] = v;
        carry = __shfl_sync(0xffffffffu, v, 31);
    }
    __syncthreads();

    float4* dst4 = (float4*)(g_integ + (((size_t)n * HF + h) * WF) * C + cb * 8);
    #pragma unroll
    for (int iter = 0; iter < 2; iter++) {
        const int idx = threadIdx.x + iter * 256;
        if (idx < 2 * WF) {
            const int grp = idx & 1;
            const int w   = idx >> 1;
            const float* trow = tile + (grp * 4) * SPITCH + w;
            float4 v;
            v.x = trow[0];
            v.y = trow[SPITCH];
            v.z = trow[2 * SPITCH];
            v.w = trow[3 * SPITCH];
            dst4[(size_t)w * (C / 4) + grp] = v;
        }
    }
}

// ---------------------------------------------------------------------------
// Kernel 2 (fused): blocks [0, 264) column-scan g_integ in place over h;
// blocks [264, ...) project grid corners.
// ---------------------------------------------------------------------------
#define NCOLB (NCAM * WF * C / 256)   // 264 column-scan blocks (exact)
__global__ void __launch_bounds__(256) colproj_kernel(
        const float* __restrict__ ks,
        const float* __restrict__ m2c,
        const float* __restrict__ prot,
        const float* __restrict__ ptran,
        const float* __restrict__ und,
        const float* __restrict__ grid) {
    const int bid = blockIdx.x;

    if (bid < NCOLB) {
        const int idx = bid * 256 + threadIdx.x;     // = (n*WF + w)*C + c
        const int n   = idx / (WF * C);
        const int rem = idx - n * (WF * C);          // w*C + c
        float* p = g_integ + (size_t)n * HF * WF * C + rem;
        const int stride = WF * C;

        float acc = 0.f;
        #pragma unroll 1
        for (int h = 0; h < HF; h += 8) {
            float v0 = p[0];
            float v1 = p[stride];
            float v2 = p[2 * stride];
            float v3 = p[3 * stride];
            float v4 = p[4 * stride];
            float v5 = p[5 * stride];
            float v6 = p[6 * stride];
            float v7 = p[7 * stride];
            acc += v0; p[0]          = acc;
            acc += v1; p[stride]     = acc;
            acc += v2; p[2 * stride] = acc;
            acc += v3; p[3 * stride] = acc;
            acc += v4; p[4 * stride] = acc;
            acc += v5; p[5 * stride] = acc;
            acc += v6; p[6 * stride] = acc;
            acc += v7; p[7 * stride] = acc;
            p += 8 * stride;
        }
        return;
    }

    // ---- projection ----
    const int id = (bid - NCOLB) * 256 + threadIdx.x;
    const int total = NCAM * NY * ZD * XD;
    if (id >= total) return;
    const int xi = id % XD;
    const int zi = (id / XD) % ZD;
    const int ny = (id / (XD * ZD)) % NY;
    const int n  = id / (XD * ZD * NY);

    const float* K  = ks    + n * 9;
    const float* M  = m2c   + n * 12;
    const float* PR = prot  + n * 9;
    const float* PT = ptran + n * 3;
    const float* Dd = und   + n * 7;

    float cal[3][4];
    #pragma unroll
    for (int i = 0; i < 3; i++)
        #pragma unroll
        for (int j = 0; j < 4; j++)
            cal[i][j] = K[i*3+0]*M[0*4+j] + K[i*3+1]*M[1*4+j] + K[i*3+2]*M[2*4+j];

    const float* g = grid + ((size_t)zi * XD + xi) * 3;
    const float vx = g[0];
    const float vy = g[1] + (2.0f - (float)ny);
    const float vz = g[2];

    float hx = cal[0][0]*vx + cal[0][1]*vy + cal[0][2]*vz + cal[0][3];
    float hy = cal[1][0]*vx + cal[1][1]*vy + cal[1][2]*vz + cal[1][3];
    float hz = cal[2][0]*vx + cal[2][1]*vy + cal[2][2]*vz + cal[2][3];

    const float posf = (hz > 0.f) ? 1.f : 0.f;
    hx *= posf; hy *= posf;
    const float px = hx / hz, py = hy / hz;

    const float cx = K[2], cy = K[5], fx = K[0], fy = K[4];
    const float x = (px - cx) / fx, y = (py - cy) / fy;

    float xd, yd;
    if (Dd[6] == 1.0f) {
        float r  = sqrtf(x*x + y*y);
        float th = atanf(r);
        float t2 = th * th;
        float t4 = t2 * t2;
        float rad = th * (1.f + Dd[0]*t2 + Dd[1]*t4 + Dd[2]*t4*t2 + Dd[5]*t4*t4) / r;
        xd = x * rad * fx + cx;
        yd = y * rad * fy + cy;
    } else {
        float r2 = x*x + y*y;
        float r4 = r2 * r2;
        float poly = 1.f + Dd[0]*r2 + Dd[1]*r4 + Dd[2]*r4*r2;
        float p1 = Dd[3], p2 = Dd[4];
        float xdd = x*poly + (2.f*p1*x*y + p2*(r2 + 2.f*x*x));
        float ydd = y*poly + (p1*(r2 + 2.f*y*y) + 2.f*p2*x*y);
        xd = xdd * fx + cx;
        yd = ydd * fy + cy;
    }
    xd *= posf; yd *= posf;

    const float qx = PR[0]*xd + PR[1]*yd + PT[0];
    const float qy = PR[3]*xd + PR[4]*yd + PT[1];

    float2 o;
    o.x = fminf(fmaxf(2.f*qx - 1.f, -1.f), 1.f);
    o.y = fminf(fmaxf(2.f*qy - 1.f, -1.f), 1.f);
    g_nc[id] = o;
}

// ---------------------------------------------------------------------------
// Kernel 3: 2 voxels per warp via LDG.128. Block 32x8 covers 16 voxels.
// Lane = (half voxel, channel quad): lanes 0-15 -> voxel A float4 texel,
// lanes 16-31 -> voxel B. One LDG.128 fetches two texels -> half the LDG
// instruction count vs float2 form. Inactive tasks get zeroed descriptors;
// warp skips a cam only when BOTH voxels are inactive.
// ---------------------------------------------------------------------------
__global__ void __launch_bounds__(256) vox_kernel(float* __restrict__ out) {
    const int nhd = blockIdx.x >> 3;             // 8 blocks per (nh,d) row
    const int d   = nhd & 127;
    const int nh  = nhd >> 7;
    const int wd0 = (blockIdx.x & 7) << 4;       // 16 voxels per block
    const int tid = threadIdx.y * 32 + threadIdx.x;

    __shared__ int   s_off[96 * 16];    // texel offsets (float4 units)
    __shared__ float s_c[96 * 16];      // combined coefficients
    __shared__ int   s_act[96];         // active flag per (cam,voxel)
    __shared__ float res[C * 17];       // output staging [ch][vloc] pitch 17

    // ---- Geometry phase: one task per thread, task = cam*16 + vloc ----
    if (tid < 96) {
        const int cam = tid >> 4, vloc = tid & 15;
        const int wd = wd0 + vloc;
        const float2* ncp = g_nc + cam * (NY * ZD * XD) + ((size_t)nh * ZD + d) * XD + wd;

        float l = 1e30f, r = -1e30f, tp = 1e30f, bt = -1e30f;
        #pragma unroll
        for (int a = 0; a < 2; a++)
            #pragma unroll
            for (int b = 0; b < 2; b++)
                #pragma unroll
                for (int cc2 = 0; cc2 < 2; cc2++) {
                    float2 p = __ldg(ncp + (a * ZD + b) * XD + cc2);
                    l  = fminf(l,  p.x); r  = fmaxf(r,  p.x);
                    tp = fminf(tp, p.y); bt = fmaxf(bt, p.y);
                }

        const float area = (r - l) * (bt - tp) * (HF * WF * 0.25f) + 1e-6f;
        const int ok = (area > 1e-6f) ? 1 : 0;
        s_act[tid] = ok;
        if (ok) {
            float pxl = fminf(fmaxf((l  + 1.f) * 87.5f, 0.f), 175.f);
            float pxr = fminf(fmaxf((r  + 1.f) * 87.5f, 0.f), 175.f);
            float pyt = fminf(fmaxf((tp + 1.f) * 31.5f, 0.f), 63.f);
            float pyb = fminf(fmaxf((bt + 1.f) * 31.5f, 0.f), 63.f);

            float fxl = floorf(pxl), fxr = floorf(pxr);
            float fyt = floorf(pyt), fyb = floorf(pyb);
            float wxl = pxl - fxl, wxr = pxr - fxr;
            float wyt = pyt - fyt, wyb = pyb - fyb;

            int xs[4], ys[4];
            xs[0] = (int)fxl; xs[1] = min(xs[0] + 1, WF - 1);
            xs[2] = (int)fxr; xs[3] = min(xs[2] + 1, WF - 1);
            ys[0] = (int)fyt; ys[1] = min(ys[0] + 1, HF - 1);
            ys[2] = (int)fyb; ys[3] = min(ys[2] + 1, HF - 1);

            const float inv = 1.0f / area;
            float cxv[4] = {1.f - wxl, wxl, -(1.f - wxr), -wxr};
            float cyv[4] = {(1.f - wyt) * inv, wyt * inv,
                            -(1.f - wyb) * inv, -wyb * inv};

            #pragma unroll
            for (int i = 0; i < 4; i++) {
                const int yb = ys[i] * WF;
                #pragma unroll
                for (int j = 0; j < 4; j++) {
                    s_off[tid * 16 + i * 4 + j] = (yb + xs[j]) * (C / 4);
                    s_c[tid * 16 + i * 4 + j]   = cyv[i] * cxv[j];
                }
            }
        } else {
            #pragma unroll
            for (int k = 0; k < 16; k++) {
                s_off[tid * 16 + k] = 0;
                s_c[tid * 16 + k]   = 0.f;
            }
        }
    }
    __syncthreads();

    // ---- Gather phase ----
    const int q    = threadIdx.x & 15;           // channel quad (4 channels)
    const int half = threadIdx.x >> 4;           // voxel within pair
    float4 m = make_float4(-3.402823466e38f, -3.402823466e38f,
                           -3.402823466e38f, -3.402823466e38f);

    #pragma unroll 1
    for (int n = 0; n < NCAM; n++) {
        const int tA = n * 16 + 2 * threadIdx.y;
        if ((s_act[tA] | s_act[tA + 1]) == 0) {
            m.x = fmaxf(m.x, 0.f); m.y = fmaxf(m.y, 0.f);
            m.z = fmaxf(m.z, 0.f); m.w = fmaxf(m.w, 0.f);
            continue;
        }
        const int task = tA + half;
        const int4*   so = (const int4*)  (s_off + task * 16);
        const float4* sc = (const float4*)(s_c   + task * 16);
        const float4* base = (const float4*)(g_integ + (size_t)n * HF * WF * C) + q;

        float4 acc = make_float4(0.f, 0.f, 0.f, 0.f);
        #pragma unroll
        for (int g = 0; g < 4; g++) {
            const int4   o  = so[g];
            const float4 cc = sc[g];
            float4 a = __ldg(base + o.x), b = __ldg(base + o.y);
            float4 c = __ldg(base + o.z), e = __ldg(base + o.w);
            acc.x = fmaf(a.x, cc.x, fmaf(b.x, cc.y, fmaf(c.x, cc.z, fmaf(e.x, cc.w, acc.x))));
            acc.y = fmaf(a.y, cc.x, fmaf(b.y, cc.y, fmaf(c.y, cc.z, fmaf(e.y, cc.w, acc.y))));
            acc.z = fmaf(a.z, cc.x, fmaf(b.z, cc.y, fmaf(c.z, cc.z, fmaf(e.z, cc.w, acc.z))));
            acc.w = fmaf(a.w, cc.x, fmaf(b.w, cc.y, fmaf(c.w, cc.z, fmaf(e.w, cc.w, acc.w))));
        }
        m.x = fmaxf(m.x, acc.x); m.y = fmaxf(m.y, acc.y);
        m.z = fmaxf(m.z, acc.z); m.w = fmaxf(m.w, acc.w);
    }

    // ---- Output staging ----
    {
        const int vloc = 2 * threadIdx.y + half;
        res[(4 * q    ) * 17 + vloc] = m.x;
        res[(4 * q + 1) * 17 + vloc] = m.y;
        res[(4 * q + 2) * 17 + vloc] = m.z;
        res[(4 * q + 3) * 17 + vloc] = m.w;
    }
    __syncthreads();

    #pragma unroll
    for (int rep = 0; rep < 4; rep++) {
        const int idx = tid + rep * 256;         // 0..1023 = ch*16 + j
        const int ch  = idx >> 4;
        const int j   = idx & 15;
        out[((size_t)(ch * NH + nh) * DD + d) * WDIM + wd0 + j] = res[ch * 17 + j];
    }
}

// ---------------------------------------------------------------------------
extern "C" void kernel_launch(void* const* d_in, const int* in_sizes, int n_in,
                              void* d_out, int out_size) {
    (void)in_sizes; (void)n_in; (void)out_size;
    const float* features  = (const float*)d_in[0];
    const float* ks        = (const float*)d_in[1];
    const float* imu2cs    = (const float*)d_in[2];
    const float* post_rots = (const float*)d_in[3];
    const float* post_trans= (const float*)d_in[4];
    const float* undists   = (const float*)d_in[5];
    const float* grid      = (const float*)d_in[6];
    float* out = (float*)d_out;

    rowscan_t_kernel<<<NCAM * HF * (C / 8), 256>>>(features);

    const int totalP = NCAM * NY * ZD * XD;
    const int projBlocks = (totalP + 255) / 256;     // 1561
    colproj_kernel<<<NCOLB + projBlocks, 256>>>(ks, imu2cs, post_rots,
                                                post_trans, undists, grid);

    dim3 blk(32, 8);
    vox_kernel<<<(NH * DD * WDIM) / 16, blk>>>(out);
}